// round 5
// baseline (speedup 1.0000x reference)
#include <cuda_runtime.h>
#include <cstdint>
#include <cstddef>

#define NUM_VARS  512
#define EMBED_DIM 32
#define IN_DIM    512
#define TOP_K     10
#define BATCH     256
#define TI        16                       // rows per tile
#define NITEMS    (BATCH * (NUM_VARS/TI))  // 8192 work items

// scratch (no allocations allowed)
__device__ float g_s[BATCH * EMBED_DIM];   // (c*c)[b][e]
__device__ float g_gate[BATCH];            // sigmoid(c@Wg+bg)

// --------------------------------------------------------------------------
// Kernel A: context MLP -> c, s=c^2, gate. One block per batch row.
// --------------------------------------------------------------------------
__global__ __launch_bounds__(128) void ctx_kernel(
    const float* __restrict__ x,    // [B, 512]
    const float* __restrict__ W1,   // [32, 512]
    const float* __restrict__ b1,   // [32]
    const float* __restrict__ W2,   // [32, 32]
    const float* __restrict__ b2,   // [32]
    const float* __restrict__ Wg,   // [32]
    const float* __restrict__ bg)   // [1]
{
    __shared__ float xs[IN_DIM];
    __shared__ float hs[EMBED_DIM];
    const int b   = blockIdx.x;
    const int tid = threadIdx.x;
    const float* xrow = x + (size_t)b * IN_DIM;
    for (int i = tid; i < IN_DIM; i += 128) xs[i] = xrow[i];
    __syncthreads();

    const int w = tid >> 5, l = tid & 31;
    // h = relu(x @ W1^T + b1): warp w computes e in [8w, 8w+8)
    for (int eo = 0; eo < 8; ++eo) {
        const int e = w * 8 + eo;
        const float* wrow = W1 + (size_t)e * IN_DIM;
        float p = 0.f;
        #pragma unroll 4
        for (int k = l; k < IN_DIM; k += 32) p = fmaf(xs[k], wrow[k], p);
        #pragma unroll
        for (int o = 16; o; o >>= 1) p += __shfl_xor_sync(0xffffffffu, p, o);
        if (l == 0) hs[e] = fmaxf(p + b1[e], 0.f);
    }
    __syncthreads();

    if (w == 0) {                      // c = h @ W2^T + b2, lane = e
        const int e = l;
        float c = b2[e];
        #pragma unroll
        for (int k = 0; k < EMBED_DIM; ++k) c = fmaf(W2[e * EMBED_DIM + k], hs[k], c);
        g_s[b * EMBED_DIM + e] = c * c;
        float gp = c * Wg[e];
        #pragma unroll
        for (int o = 16; o; o >>= 1) gp += __shfl_xor_sync(0xffffffffu, gp, o);
        if (e == 0) g_gate[b] = __fdividef(1.f, 1.f + __expf(-(gp + bg[0])));
    }
}

// --------------------------------------------------------------------------
// Kernel B: persistent adj + sigmoid + exact top-k + gated write.
// smem: ebuf (e-pair-interleaved emb, 64KB) | vbuf (16x512 f32, 32KB)
//       | abuf (16x16 float2, 2KB)
// --------------------------------------------------------------------------
#define SMEM_EBUF_BYTES (16 * NUM_VARS * 8)
#define SMEM_VBUF_BYTES (TI * NUM_VARS * 4)
#define SMEM_ABUF_BYTES (TI * 16 * 8)
#define SMEM_TOTAL (SMEM_EBUF_BYTES + SMEM_VBUF_BYTES + SMEM_ABUF_BYTES)

__global__ __launch_bounds__(256, 2) void adj_kernel(
    const float* __restrict__ emb,   // [512, 32]
    float* __restrict__ out)         // [256, 512, 512]
{
    extern __shared__ unsigned char smem_raw[];
    float2* ebuf2 = reinterpret_cast<float2*>(smem_raw);
    float*  vbuf  = reinterpret_cast<float*>(smem_raw + SMEM_EBUF_BYTES);
    float2* abuf2 = reinterpret_cast<float2*>(smem_raw + SMEM_EBUF_BYTES + SMEM_VBUF_BYTES);
    unsigned long long* ebufU = reinterpret_cast<unsigned long long*>(ebuf2);
    unsigned long long* abufU = reinterpret_cast<unsigned long long*>(abuf2);

    const int tid = threadIdx.x;

    // Stage emb once: ebuf2[ep][j] = (emb[j][2ep], emb[j][2ep+1])
    for (int idx = tid; idx < NUM_VARS * (EMBED_DIM / 2); idx += 256) {
        const int j = idx >> 4, ep = idx & 15;
        ebuf2[ep * NUM_VARS + j] = reinterpret_cast<const float2*>(emb)[idx];
    }
    __syncthreads();

    const int tj = tid & 63;     // column group (j = tj + 64q)
    const int ti = tid >> 6;     // row group   (i = ti*4 + k)
    const int w  = tid >> 5, l = tid & 31;

    for (int item = blockIdx.x; item < NITEMS; item += gridDim.x) {
        const int b  = item >> 5;
        const int i0 = (item & 31) * TI;

        // abuf2[i][ep] = emb[i0+i][2ep..2ep+1] * s[b][2ep..2ep+1]
        {
            const int i = tid >> 4, ep = tid & 15;
            float2 ev = reinterpret_cast<const float2*>(emb)[(i0 + i) * 16 + ep];
            float2 sv = reinterpret_cast<const float2*>(g_s + b * EMBED_DIM)[ep];
            ev.x *= sv.x; ev.y *= sv.y;
            abuf2[i * 16 + ep] = ev;
        }
        __syncthreads();

        // ---- main f32x2 FMA loop: 4 rows x 8 cols per thread ----
        unsigned long long acc[4][8];
        #pragma unroll
        for (int i = 0; i < 4; ++i)
            #pragma unroll
            for (int q = 0; q < 8; ++q) acc[i][q] = 0ull;

        #pragma unroll
        for (int ep = 0; ep < 16; ++ep) {
            unsigned long long a[4], bb[8];
            #pragma unroll
            for (int i = 0; i < 4; ++i) a[i] = abufU[(ti * 4 + i) * 16 + ep];   // broadcast
            #pragma unroll
            for (int q = 0; q < 8; ++q) bb[q] = ebufU[ep * NUM_VARS + tj + 64 * q];
            #pragma unroll
            for (int i = 0; i < 4; ++i)
                #pragma unroll
                for (int q = 0; q < 8; ++q)
                    asm("fma.rn.f32x2 %0, %1, %2, %0;"
                        : "+l"(acc[i][q]) : "l"(a[i]), "l"(bb[q]));
        }

        const float gate = g_gate[b];

        // ---- sigmoid epilogue -> vbuf ----
        #pragma unroll
        for (int i = 0; i < 4; ++i) {
            #pragma unroll
            for (int q = 0; q < 8; ++q) {
                const float lo = __uint_as_float((unsigned)acc[i][q]);
                const float hi = __uint_as_float((unsigned)(acc[i][q] >> 32));
                const float xv = lo + hi;
                const float v  = __fdividef(1.f, 1.f + __expf(-xv));
                vbuf[(ti * 4 + i) * NUM_VARS + q * 64 + tj] = v;
            }
        }
        __syncthreads();

        // ---- exact top-10 per row (one warp per row, 2 rows/warp) ----
        #pragma unroll 1
        for (int rr = 0; rr < 2; ++rr) {
            const int r = w * 2 + rr;
            float* row = out + ((size_t)b * NUM_VARS + (i0 + r)) * NUM_VARS;

            // zero full row (coalesced float4)
            const float4 z = make_float4(0.f, 0.f, 0.f, 0.f);
            #pragma unroll
            for (int c = 0; c < 4; ++c)
                reinterpret_cast<float4*>(row)[c * 32 + l] = z;

            float* vrow = vbuf + r * NUM_VARS;
            // lane l owns j = l + 32c ; local argmax with smallest-j-on-tie
            float lm = vrow[l]; int mj = l;
            #pragma unroll
            for (int c = 1; c < 16; ++c) {
                const float v = vrow[l + 32 * c];
                if (v > lm) { lm = v; mj = l + 32 * c; }
            }
            __syncwarp();   // order zero-stores before winner stores

            for (int it = 0; it < TOP_K; ++it) {
                float wm = lm;
                #pragma unroll
                for (int o = 16; o; o >>= 1)
                    wm = fmaxf(wm, __shfl_xor_sync(0xffffffffu, wm, o));
                const unsigned ball = __ballot_sync(0xffffffffu, lm == wm);
                int winner;
                if (__popc(ball) > 1) {          // value tie across lanes: min index wins
                    int cj = (lm == wm) ? mj : 0x7fffffff;
                    int jm = cj;
                    #pragma unroll
                    for (int o = 16; o; o >>= 1)
                        jm = min(jm, __shfl_xor_sync(0xffffffffu, jm, o));
                    const unsigned b2m = __ballot_sync(0xffffffffu, cj == jm);
                    winner = __ffs(b2m) - 1;
                } else {
                    winner = __ffs(ball) - 1;
                }
                if (l == winner) {
                    row[mj]  = wm * gate;        // write selected element
                    vrow[mj] = -1.f;             // remove (sigmoid > 0 always)
                    lm = vrow[l]; mj = l;        // rescan own 16 slots
                    #pragma unroll
                    for (int c = 1; c < 16; ++c) {
                        const float v = vrow[l + 32 * c];
                        if (v > lm) { lm = v; mj = l + 32 * c; }
                    }
                }
                __syncwarp();
            }
        }
        __syncthreads();   // vbuf/abuf reuse barrier
    }
}

// --------------------------------------------------------------------------
extern "C" void kernel_launch(void* const* d_in, const int* in_sizes, int n_in,
                              void* d_out, int out_size) {
    const float* ctx = (const float*)d_in[0];  // [256,512]
    const float* emb = (const float*)d_in[1];  // [512,32]
    const float* W1  = (const float*)d_in[2];  // [32,512]
    const float* b1  = (const float*)d_in[3];  // [32]
    const float* W2  = (const float*)d_in[4];  // [32,32]
    const float* b2  = (const float*)d_in[5];  // [32]
    const float* Wg  = (const float*)d_in[6];  // [1,32]
    const float* bg  = (const float*)d_in[7];  // [1]
    float* out = (float*)d_out;

    ctx_kernel<<<BATCH, 128>>>(ctx, W1, b1, W2, b2, Wg, bg);

    cudaFuncSetAttribute(adj_kernel,
                         cudaFuncAttributeMaxDynamicSharedMemorySize, SMEM_TOTAL);
    adj_kernel<<<304, 256, SMEM_TOTAL>>>(emb, out);
}

// round 6
// speedup vs baseline: 1.1239x; 1.1239x over previous
#include <cuda_runtime.h>
#include <cstdint>
#include <cstddef>

#define NUM_VARS  512
#define EMBED_DIM 32
#define IN_DIM    512
#define TOP_K     10
#define BATCH     256
#define TI        16                       // rows per tile
#define NITEMS    (BATCH * (NUM_VARS/TI))  // 8192 work items

// vbuf layout: row stride = 32 lanes * 20 words (16 used + 4 pad) = 640 floats
#define VROW_STRIDE 640
#define LANE_STRIDE 20

// scratch (no allocations allowed)
__device__ float g_s[BATCH * EMBED_DIM];   // (c*c)[b][e]
__device__ float g_gate[BATCH];            // sigmoid(c@Wg+bg)

// --------------------------------------------------------------------------
// Kernel A: context MLP -> c, s=c^2, gate. One block per batch row.
// --------------------------------------------------------------------------
__global__ __launch_bounds__(128) void ctx_kernel(
    const float* __restrict__ x,    // [B, 512]
    const float* __restrict__ W1,   // [32, 512]
    const float* __restrict__ b1,   // [32]
    const float* __restrict__ W2,   // [32, 32]
    const float* __restrict__ b2,   // [32]
    const float* __restrict__ Wg,   // [32]
    const float* __restrict__ bg)   // [1]
{
    __shared__ float xs[IN_DIM];
    __shared__ float hs[EMBED_DIM];
    const int b   = blockIdx.x;
    const int tid = threadIdx.x;
    const float* xrow = x + (size_t)b * IN_DIM;
    for (int i = tid; i < IN_DIM; i += 128) xs[i] = xrow[i];
    __syncthreads();

    const int w = tid >> 5, l = tid & 31;
    for (int eo = 0; eo < 8; ++eo) {
        const int e = w * 8 + eo;
        const float* wrow = W1 + (size_t)e * IN_DIM;
        float p = 0.f;
        #pragma unroll 4
        for (int k = l; k < IN_DIM; k += 32) p = fmaf(xs[k], wrow[k], p);
        #pragma unroll
        for (int o = 16; o; o >>= 1) p += __shfl_xor_sync(0xffffffffu, p, o);
        if (l == 0) hs[e] = fmaxf(p + b1[e], 0.f);
    }
    __syncthreads();

    if (w == 0) {
        const int e = l;
        float c = b2[e];
        #pragma unroll
        for (int k = 0; k < EMBED_DIM; ++k) c = fmaf(W2[e * EMBED_DIM + k], hs[k], c);
        g_s[b * EMBED_DIM + e] = c * c;
        float gp = c * Wg[e];
        #pragma unroll
        for (int o = 16; o; o >>= 1) gp += __shfl_xor_sync(0xffffffffu, gp, o);
        if (e == 0) g_gate[b] = __fdividef(1.f, 1.f + __expf(-(gp + bg[0])));
    }
}

// --------------------------------------------------------------------------
// Kernel B: persistent adj + sigmoid + exact top-k + gated write.
// smem: ebuf4 [8 ef][512 j] float4  (64 KB)
//       vbuf  [16 rows][640]  f32   (40 KB, lane-contiguous, pad 20)
//       abuf4 [16 rows][8 ef] float4 (2 KB)
// --------------------------------------------------------------------------
#define SMEM_EBUF_BYTES (8 * NUM_VARS * 16)
#define SMEM_VBUF_BYTES (TI * VROW_STRIDE * 4)
#define SMEM_ABUF_BYTES (TI * 8 * 16)
#define SMEM_TOTAL (SMEM_EBUF_BYTES + SMEM_VBUF_BYTES + SMEM_ABUF_BYTES)

__global__ __launch_bounds__(256, 2) void adj_kernel(
    const float* __restrict__ emb,   // [512, 32]
    float* __restrict__ out)         // [256, 512, 512]
{
    extern __shared__ unsigned char smem_raw[];
    float4* ebuf4 = reinterpret_cast<float4*>(smem_raw);
    float*  vbuf  = reinterpret_cast<float*>(smem_raw + SMEM_EBUF_BYTES);
    float2* abuf2 = reinterpret_cast<float2*>(smem_raw + SMEM_EBUF_BYTES + SMEM_VBUF_BYTES);
    ulonglong2* ebufU2 = reinterpret_cast<ulonglong2*>(ebuf4);
    ulonglong2* abufU2 = reinterpret_cast<ulonglong2*>(abuf2);

    const int tid = threadIdx.x;

    // Stage emb once: ebuf4[ef][j] = emb[j][4ef..4ef+3]
    for (int idx = tid; idx < NUM_VARS * 8; idx += 256) {
        const int j = idx >> 3, ef = idx & 7;
        ebuf4[ef * NUM_VARS + j] = reinterpret_cast<const float4*>(emb)[idx];
    }
    __syncthreads();

    const int tj = tid & 63;     // column group (j = tj + 64q)
    const int ti = tid >> 6;     // row group   (i = ti*4 + k)
    const int w  = tid >> 5, l = tid & 31;
    const int tjoff = ((tj >> 4) * LANE_STRIDE) + (tj & 15);  // vbuf col offset

    for (int item = blockIdx.x; item < NITEMS; item += gridDim.x) {
        const int b  = item >> 5;
        const int i0 = (item & 31) * TI;

        // abuf[i][e-pair] = emb[i0+i][2ep..2ep+1] * s[b][2ep..2ep+1]
        {
            const int i = tid >> 4, ep = tid & 15;
            float2 ev = reinterpret_cast<const float2*>(emb)[(i0 + i) * 16 + ep];
            float2 sv = reinterpret_cast<const float2*>(g_s + b * EMBED_DIM)[ep];
            ev.x *= sv.x; ev.y *= sv.y;
            abuf2[i * 16 + ep] = ev;
        }
        __syncthreads();

        // ---- main f32x2 FMA loop: 4 rows x 8 cols, float4 (2 e-pairs) steps ----
        unsigned long long acc[4][8];
        #pragma unroll
        for (int i = 0; i < 4; ++i)
            #pragma unroll
            for (int q = 0; q < 8; ++q) acc[i][q] = 0ull;

        #pragma unroll
        for (int ef = 0; ef < 8; ++ef) {
            ulonglong2 av[4];
            #pragma unroll
            for (int i = 0; i < 4; ++i) av[i] = abufU2[(ti * 4 + i) * 8 + ef]; // broadcast
            #pragma unroll
            for (int q = 0; q < 8; ++q) {
                const ulonglong2 bv = ebufU2[ef * NUM_VARS + tj + 64 * q];
                #pragma unroll
                for (int i = 0; i < 4; ++i) {
                    asm("fma.rn.f32x2 %0, %1, %2, %0;"
                        : "+l"(acc[i][q]) : "l"(av[i].x), "l"(bv.x));
                    asm("fma.rn.f32x2 %0, %1, %2, %0;"
                        : "+l"(acc[i][q]) : "l"(av[i].y), "l"(bv.y));
                }
            }
        }

        const float gate = g_gate[b];

        // ---- sigmoid epilogue -> vbuf (lane-contiguous layout) ----
        #pragma unroll
        for (int i = 0; i < 4; ++i) {
            #pragma unroll
            for (int q = 0; q < 8; ++q) {
                const float lo = __uint_as_float((unsigned)acc[i][q]);
                const float hi = __uint_as_float((unsigned)(acc[i][q] >> 32));
                const float xv = lo + hi;
                const float v  = __fdividef(1.f, 1.f + __expf(-xv));
                vbuf[(ti * 4 + i) * VROW_STRIDE + q * (4 * LANE_STRIDE) + tjoff] = v;
            }
        }
        __syncthreads();

        // ---- exact top-10 per row (one warp per row, 2 rows/warp) ----
        // lane l owns j in [16l, 16l+16) at vrow[20l + c]; ascending disjoint
        // ownership => on value ties, min index == lowest lane => __ffs only.
        #pragma unroll 1
        for (int rr = 0; rr < 2; ++rr) {
            const int r = w * 2 + rr;
            float* row = out + ((size_t)b * NUM_VARS + (i0 + r)) * NUM_VARS;

            // zero full row (coalesced float4)
            const float4 z = make_float4(0.f, 0.f, 0.f, 0.f);
            #pragma unroll
            for (int c = 0; c < 4; ++c)
                reinterpret_cast<float4*>(row)[c * 32 + l] = z;

            const float* lptr = vbuf + r * VROW_STRIDE + l * LANE_STRIDE;
            // local argmax over 16 owned values (u32 bits; strict > keeps min idx)
            unsigned lm = 0u; int mj = l * 16;
            #pragma unroll
            for (int cc = 0; cc < 4; ++cc) {
                const float4 vv = reinterpret_cast<const float4*>(lptr)[cc];
                unsigned bx;
                bx = __float_as_uint(vv.x); if (bx > lm) { lm = bx; mj = l*16 + 4*cc + 0; }
                bx = __float_as_uint(vv.y); if (bx > lm) { lm = bx; mj = l*16 + 4*cc + 1; }
                bx = __float_as_uint(vv.z); if (bx > lm) { lm = bx; mj = l*16 + 4*cc + 2; }
                bx = __float_as_uint(vv.w); if (bx > lm) { lm = bx; mj = l*16 + 4*cc + 3; }
            }
            __syncwarp();   // order zero-stores before winner stores

            #pragma unroll 1
            for (int it = 0; it < TOP_K; ++it) {
                unsigned wm;
                asm("redux.sync.max.u32 %0, %1, 0xffffffff;" : "=r"(wm) : "r"(lm));
                const unsigned ball = __ballot_sync(0xffffffffu, lm == wm);
                const int winner = __ffs(ball) - 1;   // min index on ties
                if (l == winner) {
                    row[mj] = __uint_as_float(wm) * gate;   // selected element
                    if (it < TOP_K - 1) {
                        // remove and rescan own 16 slots
                        *(float*)(lptr + (mj & 15)) = 0.f;  // sentinel: bits 0
                        lm = 0u; mj = l * 16;
                        #pragma unroll
                        for (int cc = 0; cc < 4; ++cc) {
                            const float4 vv = reinterpret_cast<const float4*>(lptr)[cc];
                            unsigned bx;
                            bx = __float_as_uint(vv.x); if (bx > lm) { lm = bx; mj = l*16 + 4*cc + 0; }
                            bx = __float_as_uint(vv.y); if (bx > lm) { lm = bx; mj = l*16 + 4*cc + 1; }
                            bx = __float_as_uint(vv.z); if (bx > lm) { lm = bx; mj = l*16 + 4*cc + 2; }
                            bx = __float_as_uint(vv.w); if (bx > lm) { lm = bx; mj = l*16 + 4*cc + 3; }
                        }
                    }
                }
                // no __syncwarp needed: each lane reads/writes only its own
                // vbuf slots; redux/ballot reconverge the warp.
            }
        }
        __syncthreads();   // vbuf/abuf reuse barrier
    }
}

// --------------------------------------------------------------------------
extern "C" void kernel_launch(void* const* d_in, const int* in_sizes, int n_in,
                              void* d_out, int out_size) {
    const float* ctx = (const float*)d_in[0];  // [256,512]
    const float* emb = (const float*)d_in[1];  // [512,32]
    const float* W1  = (const float*)d_in[2];  // [32,512]
    const float* b1  = (const float*)d_in[3];  // [32]
    const float* W2  = (const float*)d_in[4];  // [32,32]
    const float* b2  = (const float*)d_in[5];  // [32]
    const float* Wg  = (const float*)d_in[6];  // [1,32]
    const float* bg  = (const float*)d_in[7];  // [1]
    float* out = (float*)d_out;

    ctx_kernel<<<BATCH, 128>>>(ctx, W1, b1, W2, b2, Wg, bg);

    cudaFuncSetAttribute(adj_kernel,
                         cudaFuncAttributeMaxDynamicSharedMemorySize, SMEM_TOTAL);
    adj_kernel<<<304, 256, SMEM_TOTAL>>>(emb, out);
}